// round 2
// baseline (speedup 1.0000x reference)
#include <cuda_runtime.h>

// Shapes are fixed by the problem: B=32, S=4096, H=1024, fp32.
#define BB 32
#define SS 4096
#define HH 1024
#define CHUNKS 32
#define ROWS_PER (SS / CHUNKS)   // 128 rows of S per CTA
#define THREADS 256
#define VPT (HH / THREADS)       // 4 floats per thread
#define EPS 1e-5f

// Partial results scratch (allowed: static __device__ arrays, no allocation).
__device__ float g_acc[BB][CHUNKS][HH];   // 4 MiB
__device__ float g_m[BB][CHUNKS];
__device__ float g_l[BB][CHUNKS];
__device__ float g_cmu[BB][CHUNKS];

// Block-wide 3-way sum reduction; every thread receives identical results.
__device__ __forceinline__ float3 blockReduce3(float a, float b, float c, float* sm) {
    #pragma unroll
    for (int off = 16; off > 0; off >>= 1) {
        a += __shfl_xor_sync(0xffffffffu, a, off);
        b += __shfl_xor_sync(0xffffffffu, b, off);
        c += __shfl_xor_sync(0xffffffffu, c, off);
    }
    const int wid  = threadIdx.x >> 5;
    const int lane = threadIdx.x & 31;
    if (lane == 0) { sm[wid] = a; sm[8 + wid] = b; sm[16 + wid] = c; }
    __syncthreads();
    if (threadIdx.x < 32) {
        float a2 = (lane < 8) ? sm[lane]      : 0.f;
        float b2 = (lane < 8) ? sm[8 + lane]  : 0.f;
        float c2 = (lane < 8) ? sm[16 + lane] : 0.f;
        #pragma unroll
        for (int off = 4; off > 0; off >>= 1) {
            a2 += __shfl_xor_sync(0xffffffffu, a2, off);
            b2 += __shfl_xor_sync(0xffffffffu, b2, off);
            c2 += __shfl_xor_sync(0xffffffffu, c2, off);
        }
        if (lane == 0) { sm[24] = a2; sm[25] = b2; sm[26] = c2; }
    }
    __syncthreads();
    float3 r;
    r.x = sm[24]; r.y = sm[25]; r.z = sm[26];
    __syncthreads();   // protect smem before next round's writes
    return r;
}

// Pass 1: per (batch, S-chunk) CTA — single read of x, online softmax pooling.
__global__ void __launch_bounds__(THREADS)
ln_attn_pass1(const float* __restrict__ x,
              const float* __restrict__ gamma,
              const float* __restrict__ attw) {
    __shared__ float sm[32];
    const int b = blockIdx.y;
    const int c = blockIdx.x;
    const int t = threadIdx.x;
    const int h0 = t * VPT;

    // gw = gamma * attn_w (4 per thread), and Sgw = sum(gw)
    float4 g4 = *reinterpret_cast<const float4*>(gamma + h0);
    float4 w4 = *reinterpret_cast<const float4*>(attw + h0);
    float4 gw;
    gw.x = g4.x * w4.x; gw.y = g4.y * w4.y; gw.z = g4.z * w4.z; gw.w = g4.w * w4.w;
    float3 t3 = blockReduce3(gw.x + gw.y + gw.z + gw.w, 0.f, 0.f, sm);
    const float Sgw = t3.x;

    const float4* base = reinterpret_cast<const float4*>(
        x + ((size_t)b * SS + (size_t)c * ROWS_PER) * HH);

    float m = -1e30f, l = 0.f, cmu = 0.f;
    float4 acc = make_float4(0.f, 0.f, 0.f, 0.f);

    float4 xc = base[t];   // prefetch first row
    for (int s = 0; s < ROWS_PER; ++s) {
        float4 xn = xc;
        if (s + 1 < ROWS_PER)
            xn = base[(size_t)(s + 1) * (HH / 4) + t];   // prefetch next row

        float sum = xc.x + xc.y + xc.z + xc.w;
        float ssq = xc.x * xc.x + xc.y * xc.y + xc.z * xc.z + xc.w * xc.w;
        float dot = xc.x * gw.x + xc.y * gw.y + xc.z * gw.z + xc.w * gw.w;

        float3 r3 = blockReduce3(sum, ssq, dot, sm);
        const float inv_h = 1.f / (float)HH;
        float mu   = r3.x * inv_h;
        float var  = r3.y * inv_h - mu * mu;
        float rstd = rsqrtf(var + EPS);
        float score = rstd * (r3.z - mu * Sgw);

        if (score > m) {
            float scale = __expf(m - score);   // 0 on first iteration
            l *= scale; cmu *= scale;
            acc.x *= scale; acc.y *= scale; acc.z *= scale; acc.w *= scale;
            m = score;
        }
        float p  = __expf(score - m);
        float pr = p * rstd;
        l   += p;
        cmu += pr * mu;
        acc.x += pr * xc.x; acc.y += pr * xc.y;
        acc.z += pr * xc.z; acc.w += pr * xc.w;

        xc = xn;
    }

    *reinterpret_cast<float4*>(&g_acc[b][c][h0]) = acc;
    if (t == 0) { g_m[b][c] = m; g_l[b][c] = l; g_cmu[b][c] = cmu; }
}

// Pass 2: merge partials per batch, apply gamma/beta, write out[b, h].
__global__ void __launch_bounds__(THREADS)
ln_attn_pass2(const float* __restrict__ gamma,
              const float* __restrict__ beta,
              float* __restrict__ out) {
    const int b = blockIdx.x;
    const int t = threadIdx.x;
    const int h0 = t * VPT;

    float M = -1e30f;
    #pragma unroll
    for (int c = 0; c < CHUNKS; ++c) M = fmaxf(M, g_m[b][c]);

    float L = 0.f, CMU = 0.f;
    float4 A = make_float4(0.f, 0.f, 0.f, 0.f);
    #pragma unroll
    for (int c = 0; c < CHUNKS; ++c) {
        float e = __expf(g_m[b][c] - M);
        L   += g_l[b][c]   * e;
        CMU += g_cmu[b][c] * e;
        float4 a = *reinterpret_cast<const float4*>(&g_acc[b][c][h0]);
        A.x += a.x * e; A.y += a.y * e; A.z += a.z * e; A.w += a.w * e;
    }
    const float inv = 1.f / L;
    float4 g4 = *reinterpret_cast<const float4*>(gamma + h0);
    float4 b4 = *reinterpret_cast<const float4*>(beta  + h0);
    float4 o;
    o.x = g4.x * (A.x - CMU) * inv + b4.x;
    o.y = g4.y * (A.y - CMU) * inv + b4.y;
    o.z = g4.z * (A.z - CMU) * inv + b4.z;
    o.w = g4.w * (A.w - CMU) * inv + b4.w;
    *reinterpret_cast<float4*>(out + (size_t)b * HH + h0) = o;
}

extern "C" void kernel_launch(void* const* d_in, const int* in_sizes, int n_in,
                              void* d_out, int out_size) {
    const float* x     = (const float*)d_in[0];   // [B,S,H]
    const float* gamma = (const float*)d_in[1];   // [H]
    const float* beta  = (const float*)d_in[2];   // [H]
    const float* attw  = (const float*)d_in[3];   // [H]
    float* out = (float*)d_out;                   // [B,H]
    (void)in_sizes; (void)n_in; (void)out_size;

    dim3 grid1(CHUNKS, BB);
    ln_attn_pass1<<<grid1, THREADS>>>(x, gamma, attw);
    ln_attn_pass2<<<BB, THREADS>>>(gamma, beta, out);
}

// round 3
// speedup vs baseline: 1.5805x; 1.5805x over previous
#include <cuda_runtime.h>

// Shapes fixed by the problem: B=32, S=4096, H=1024, fp32.
#define BB 32
#define SS 4096
#define HH 1024
#define H4 (HH / 4)          // 256 float4 per row
#define CHUNKS 32
#define ROWS_PER (SS / CHUNKS)   // 128 rows per CTA
#define THREADS 256
#define WARPS 8
#define ROWS_PER_WARP (ROWS_PER / WARPS)   // 16
#define K4 (H4 / 32)         // 8 float4 per lane per row
#define EPS 1e-5f

// Partial results scratch (static device arrays: allocation-free).
__device__ float4 g_acc[BB][CHUNKS][H4];   // 4 MiB
__device__ float g_m[BB][CHUNKS];
__device__ float g_l[BB][CHUNKS];
__device__ float g_cmu[BB][CHUNKS];

// ---------------------------------------------------------------------------
// Pass 1: CTA = (chunk c, batch b). Warp w owns rows s = w, w+8, ... (16 rows).
// Lane l covers float4 columns k*32+l, k=0..7. All row reductions are
// warp-local shuffles -> no barriers in the hot loop.
// ---------------------------------------------------------------------------
__global__ void __launch_bounds__(THREADS, 2)
ln_attn_pass1(const float* __restrict__ x,
              const float* __restrict__ gamma,
              const float* __restrict__ attw) {
    __shared__ float4 s_gw[H4];          // 4 KB: gamma * attn_w
    __shared__ float  s_red[WARPS];
    __shared__ float  s_m[WARPS], s_l[WARPS], s_cmu[WARPS];
    __shared__ float4 s_acc[WARPS * H4]; // 32 KB: per-warp accumulators

    const int b = blockIdx.y;
    const int c = blockIdx.x;
    const int t = threadIdx.x;
    const int w = t >> 5;
    const int l = t & 31;

    // gw = gamma * attn_w, and Sgw = sum(gw)
    float4 g4 = reinterpret_cast<const float4*>(gamma)[t];
    float4 w4 = reinterpret_cast<const float4*>(attw)[t];
    float4 gwt;
    gwt.x = g4.x * w4.x; gwt.y = g4.y * w4.y; gwt.z = g4.z * w4.z; gwt.w = g4.w * w4.w;
    s_gw[t] = gwt;
    float sg = gwt.x + gwt.y + gwt.z + gwt.w;
    #pragma unroll
    for (int off = 16; off > 0; off >>= 1) sg += __shfl_xor_sync(0xffffffffu, sg, off);
    if (l == 0) s_red[w] = sg;
    __syncthreads();
    float Sgw = 0.f;
    #pragma unroll
    for (int i = 0; i < WARPS; ++i) Sgw += s_red[i];

    const float4* base = reinterpret_cast<const float4*>(
        x + ((size_t)b * SS + (size_t)c * ROWS_PER) * HH);

    float m = -1e30f, lacc = 0.f, cmu = 0.f;
    float4 acc[K4];
    #pragma unroll
    for (int k = 0; k < K4; ++k) acc[k] = make_float4(0.f, 0.f, 0.f, 0.f);

    // prefetch first row of this warp
    float4 xc[K4], xn[K4];
    {
        const float4* rp = base + (size_t)w * H4;
        #pragma unroll
        for (int k = 0; k < K4; ++k) xc[k] = rp[k * 32 + l];
    }

    for (int i = 0; i < ROWS_PER_WARP; ++i) {
        // issue next row's loads early (double buffer)
        if (i + 1 < ROWS_PER_WARP) {
            const float4* rp = base + ((size_t)w + (size_t)(i + 1) * WARPS) * H4;
            #pragma unroll
            for (int k = 0; k < K4; ++k) xn[k] = rp[k * 32 + l];
        }

        float sum = 0.f, ssq = 0.f, dot = 0.f;
        #pragma unroll
        for (int k = 0; k < K4; ++k) {
            float4 v = xc[k];
            float4 gw = s_gw[k * 32 + l];
            sum += v.x + v.y + v.z + v.w;
            ssq += v.x * v.x + v.y * v.y + v.z * v.z + v.w * v.w;
            dot += v.x * gw.x + v.y * gw.y + v.z * gw.z + v.w * gw.w;
        }
        #pragma unroll
        for (int off = 16; off > 0; off >>= 1) {
            sum += __shfl_xor_sync(0xffffffffu, sum, off);
            ssq += __shfl_xor_sync(0xffffffffu, ssq, off);
            dot += __shfl_xor_sync(0xffffffffu, dot, off);
        }

        const float inv_h = 1.f / (float)HH;
        float mu   = sum * inv_h;
        float var  = ssq * inv_h - mu * mu;
        float rstd = rsqrtf(var + EPS);
        float score = rstd * (dot - mu * Sgw);

        if (score > m) {
            float sc = __expf(m - score);    // 0 on first iteration
            lacc *= sc; cmu *= sc;
            #pragma unroll
            for (int k = 0; k < K4; ++k) {
                acc[k].x *= sc; acc[k].y *= sc; acc[k].z *= sc; acc[k].w *= sc;
            }
            m = score;
        }
        float p  = __expf(score - m);
        float pr = p * rstd;
        lacc += p;
        cmu  += pr * mu;
        #pragma unroll
        for (int k = 0; k < K4; ++k) {
            acc[k].x += pr * xc[k].x; acc[k].y += pr * xc[k].y;
            acc[k].z += pr * xc[k].z; acc[k].w += pr * xc[k].w;
        }

        #pragma unroll
        for (int k = 0; k < K4; ++k) xc[k] = xn[k];
    }

    // merge 8 warp partials within the CTA
    #pragma unroll
    for (int k = 0; k < K4; ++k) s_acc[w * H4 + k * 32 + l] = acc[k];
    if (l == 0) { s_m[w] = m; s_l[w] = lacc; s_cmu[w] = cmu; }
    __syncthreads();

    float M = -1e30f;
    #pragma unroll
    for (int wp = 0; wp < WARPS; ++wp) M = fmaxf(M, s_m[wp]);
    float L = 0.f, CMU = 0.f, ew[WARPS];
    #pragma unroll
    for (int wp = 0; wp < WARPS; ++wp) {
        ew[wp] = __expf(s_m[wp] - M);
        L   += s_l[wp]   * ew[wp];
        CMU += s_cmu[wp] * ew[wp];
    }
    // thread t sums float4 column t across the 8 warp copies
    float4 A = make_float4(0.f, 0.f, 0.f, 0.f);
    #pragma unroll
    for (int wp = 0; wp < WARPS; ++wp) {
        float4 a = s_acc[wp * H4 + t];
        float e = ew[wp];
        A.x += a.x * e; A.y += a.y * e; A.z += a.z * e; A.w += a.w * e;
    }
    g_acc[b][c][t] = A;
    if (t == 0) { g_m[b][c] = M; g_l[b][c] = L; g_cmu[b][c] = CMU; }
}

// ---------------------------------------------------------------------------
// Pass 2: grid (B, 8 H-segments), 256 threads. Thread group q = t>>5 handles
// 4 chunks; lane handles one float4 column; smem-reduce 8 partials.
// ---------------------------------------------------------------------------
__global__ void __launch_bounds__(THREADS)
ln_attn_pass2(const float* __restrict__ gamma,
              const float* __restrict__ beta,
              float* __restrict__ out) {
    __shared__ float4 s_p[8][32];
    const int b   = blockIdx.x;
    const int seg = blockIdx.y;
    const int t   = threadIdx.x;
    const int q   = t >> 5;
    const int ln  = t & 31;
    const int h4  = seg * 32 + ln;

    float M = -1e30f;
    #pragma unroll
    for (int c = 0; c < CHUNKS; ++c) M = fmaxf(M, g_m[b][c]);
    float L = 0.f, CMU = 0.f;
    #pragma unroll
    for (int c = 0; c < CHUNKS; ++c) {
        float e = __expf(g_m[b][c] - M);
        L   += g_l[b][c]   * e;
        CMU += g_cmu[b][c] * e;
    }

    float4 A = make_float4(0.f, 0.f, 0.f, 0.f);
    #pragma unroll
    for (int j = 0; j < 4; ++j) {
        int c = q * 4 + j;
        float e = __expf(g_m[b][c] - M);
        float4 a = g_acc[b][c][h4];
        A.x += a.x * e; A.y += a.y * e; A.z += a.z * e; A.w += a.w * e;
    }
    s_p[q][ln] = A;
    __syncthreads();

    if (q == 0) {
        float4 T = make_float4(0.f, 0.f, 0.f, 0.f);
        #pragma unroll
        for (int j = 0; j < 8; ++j) {
            float4 a = s_p[j][ln];
            T.x += a.x; T.y += a.y; T.z += a.z; T.w += a.w;
        }
        const float inv = 1.f / L;
        float4 g4 = reinterpret_cast<const float4*>(gamma)[h4];
        float4 b4 = reinterpret_cast<const float4*>(beta)[h4];
        float4 o;
        o.x = g4.x * (T.x - CMU) * inv + b4.x;
        o.y = g4.y * (T.y - CMU) * inv + b4.y;
        o.z = g4.z * (T.z - CMU) * inv + b4.z;
        o.w = g4.w * (T.w - CMU) * inv + b4.w;
        reinterpret_cast<float4*>(out + (size_t)b * HH)[h4] = o;
    }
}

extern "C" void kernel_launch(void* const* d_in, const int* in_sizes, int n_in,
                              void* d_out, int out_size) {
    const float* x     = (const float*)d_in[0];   // [B,S,H]
    const float* gamma = (const float*)d_in[1];   // [H]
    const float* beta  = (const float*)d_in[2];   // [H]
    const float* attw  = (const float*)d_in[3];   // [H]
    float* out = (float*)d_out;                   // [B,H]
    (void)in_sizes; (void)n_in; (void)out_size;

    dim3 grid1(CHUNKS, BB);
    ln_attn_pass1<<<grid1, THREADS>>>(x, gamma, attw);
    dim3 grid2(BB, 8);
    ln_attn_pass2<<<grid2, THREADS>>>(gamma, beta, out);
}